// round 2
// baseline (speedup 1.0000x reference)
#include <cuda_runtime.h>
#include <cstdint>

#define NNODES 50000
#define FEDGE  128
#define HDIM   256

// ---------------- scratch (no allocations allowed) ----------------
static __device__ float g_mean[NNODES * FEDGE];   // 25.6 MB
static __device__ float g_cnt[NNODES];
static __device__ float g_node1[NNODES * HDIM];   // 51.2 MB
static __device__ float g_node2[NNODES * HDIM];   // 51.2 MB
static __device__ float g_ps[NNODES];
static __device__ float g_pd[NNODES];

__device__ __forceinline__ int clamp_idx(int v) {
    v = v < 0 ? 0 : v;
    return v >= NNODES ? NNODES - 1 : v;
}

// ---------------- kernel 0: zero the accumulators ----------------
__global__ void zero_kernel() {
    int i = blockIdx.x * blockDim.x + threadIdx.x;
    const int total4 = (NNODES * FEDGE) / 4;
    if (i < total4)
        reinterpret_cast<float4*>(g_mean)[i] = make_float4(0.f, 0.f, 0.f, 0.f);
    if (i < NNODES) g_cnt[i] = 0.f;
}

// ---------------- kernel 1: scatter-add (vector atomics) ----------------
// One warp per edge: 32 lanes x float4 = 128 features.
__global__ void scatter_kernel(const float* __restrict__ edge_attr,
                               const int* __restrict__ edge_index,
                               int E) {
    int gt = blockIdx.x * blockDim.x + threadIdx.x;
    int e = gt >> 5;
    int lane = gt & 31;
    if (e >= E) return;
    int src = clamp_idx(edge_index[e]);   // broadcast load, single sector per warp
    float4 v = reinterpret_cast<const float4*>(edge_attr + (size_t)e * FEDGE)[lane];
    float* dst = g_mean + (size_t)src * FEDGE + lane * 4;
    asm volatile("red.global.add.v4.f32 [%0], {%1,%2,%3,%4};"
                 :: "l"(dst), "f"(v.x), "f"(v.y), "f"(v.z), "f"(v.w) : "memory");
    if (lane == 0) atomicAdd(g_cnt + src, 1.0f);
}

// ---------------- kernel 2: divide by counts ----------------
__global__ void mean_div_kernel() {
    int i = blockIdx.x * blockDim.x + threadIdx.x;
    if (i < NNODES * FEDGE) {
        float c = g_cnt[i >> 7];               // FEDGE == 128
        g_mean[i] *= (1.0f / fmaxf(c, 1.0f));
    }
}

// ---------------- kernel 3: fused GEMM + bias + sigmoid ----------------
// C[M,256] = sigmoid([A1 | A2] @ W + b), A2 = g_mean (row stride 128).
// Block: 128 threads. Each thread owns cols (t, t+128); block does 32 rows.
// Inner loop: per k -> 2 LDG (W, L2-hot), 32 broadcast LDS, 64 FFMA.
template <int K>
__global__ void gemm_sigmoid_kernel(const float* __restrict__ A1, int K1,
                                    const float* __restrict__ A2,
                                    const float* __restrict__ W,
                                    const float* __restrict__ b,
                                    float* __restrict__ out, int M) {
    __shared__ float As[32 * K];               // 32KB (K=256) / 48KB (K=384)
    const int tid = threadIdx.x;               // 0..127
    const int row0 = blockIdx.x * 32;

    // cooperative tile load: coalesced on k, conflict-free STS
    for (int idx = tid; idx < 32 * K; idx += 128) {
        int r = idx / K;
        int k = idx - r * K;
        int row = row0 + r;
        float v = 0.f;
        if (row < M)
            v = (k < K1) ? A1[(size_t)row * K1 + k]
                         : A2[(size_t)row * FEDGE + (k - K1)];
        As[idx] = v;
    }
    __syncthreads();

    float acc0[32], acc1[32];
#pragma unroll
    for (int r = 0; r < 32; r++) { acc0[r] = 0.f; acc1[r] = 0.f; }

    const int j0 = tid, j1 = tid + 128;
    for (int k = 0; k < K; k++) {
        float w0v = W[(size_t)k * HDIM + j0];
        float w1v = W[(size_t)k * HDIM + j1];
#pragma unroll
        for (int r = 0; r < 32; r++) {
            float a = As[r * K + k];           // warp-broadcast LDS
            acc0[r] += a * w0v;
            acc1[r] += a * w1v;
        }
    }

    float bv0 = b[j0], bv1 = b[j1];
#pragma unroll
    for (int r = 0; r < 32; r++) {
        int row = row0 + r;
        if (row < M) {
            float x0 = acc0[r] + bv0;
            float x1 = acc1[r] + bv1;
            out[(size_t)row * HDIM + j0] = 1.0f / (1.0f + __expf(-x0));
            out[(size_t)row * HDIM + j1] = 1.0f / (1.0f + __expf(-x1));
        }
    }
}

// ---------------- kernel 4: per-node partial dot products for logits ----------------
// ps[n] = node2[n] . wf[0:256]; pd[n] = node2[n] . wf[256:512]
__global__ void pspd_kernel(const float* __restrict__ wf, int Nn) {
    int gt = blockIdx.x * blockDim.x + threadIdx.x;
    int n = gt >> 5;
    int lane = gt & 31;
    if (n >= Nn) return;
    const float* row = g_node2 + (size_t)n * HDIM;
    float s = 0.f, d = 0.f;
#pragma unroll
    for (int k = lane; k < HDIM; k += 32) {
        float v = row[k];
        s += v * wf[k];
        d += v * wf[HDIM + k];
    }
#pragma unroll
    for (int o = 16; o; o >>= 1) {
        s += __shfl_xor_sync(0xFFFFFFFFu, s, o);
        d += __shfl_xor_sync(0xFFFFFFFFu, d, o);
    }
    if (lane == 0) { g_ps[n] = s; g_pd[n] = d; }
}

// ---------------- kernel 5: edge embeddings + logits ----------------
// One warp per edge: gather node2[s], node2[d] (L2-resident), stream out 2KB.
__global__ void edge_kernel(const int* __restrict__ edge_index,
                            const float* __restrict__ bf,
                            float* __restrict__ out, int E) {
    int gt = blockIdx.x * blockDim.x + threadIdx.x;
    int e = gt >> 5;
    int lane = gt & 31;
    if (e >= E) return;
    int s = clamp_idx(edge_index[e]);
    int d = clamp_idx(edge_index[E + e]);
    const float4* rs = reinterpret_cast<const float4*>(g_node2 + (size_t)s * HDIM);
    const float4* rd = reinterpret_cast<const float4*>(g_node2 + (size_t)d * HDIM);
    float4* o4 = reinterpret_cast<float4*>(out + (size_t)E + (size_t)e * (2 * HDIM));
    o4[lane]      = rs[lane];        // 256 floats = 64 float4 per half-row
    o4[32 + lane] = rs[32 + lane];
    o4[64 + lane] = rd[lane];
    o4[96 + lane] = rd[32 + lane];
    if (lane == 0) out[e] = g_ps[s] + g_pd[d] + bf[0];
}

// ---------------- launch ----------------
extern "C" void kernel_launch(void* const* d_in, const int* in_sizes, int n_in,
                              void* d_out, int out_size) {
    const float* edge_attr  = (const float*)d_in[0];
    const int*   edge_index = (const int*)d_in[1];   // harness dtype contract: int32
    const float* node_attr  = (const float*)d_in[2];
    const float* w0 = (const float*)d_in[3];
    const float* b0 = (const float*)d_in[4];
    const float* w1 = (const float*)d_in[5];
    const float* b1 = (const float*)d_in[6];
    const float* wf = (const float*)d_in[7];
    const float* bf = (const float*)d_in[8];
    float* out = (float*)d_out;

    const int E  = in_sizes[1] / 2;
    const int Nn = in_sizes[2] / FEDGE;

    float *mean_p, *node1_p, *node2_p;
    cudaGetSymbolAddress((void**)&mean_p,  g_mean);
    cudaGetSymbolAddress((void**)&node1_p, g_node1);
    cudaGetSymbolAddress((void**)&node2_p, g_node2);

    // 0: zero accumulators
    {
        int total4 = (NNODES * FEDGE) / 4;
        zero_kernel<<<(total4 + 255) / 256, 256>>>();
    }
    // 1: scatter-add (warp per edge)
    {
        long long threads = (long long)E * 32;
        int blocks = (int)((threads + 255) / 256);
        scatter_kernel<<<blocks, 256>>>(edge_attr, edge_index, E);
    }
    // 2: mean = agg / max(cnt,1)
    mean_div_kernel<<<(NNODES * FEDGE + 255) / 256, 256>>>();

    // 3: layer 0  (A1 = node_attr K1=128, A2 = mean) -> node1
    gemm_sigmoid_kernel<256><<<(Nn + 31) / 32, 128>>>(node_attr, FEDGE, mean_p,
                                                      w0, b0, node1_p, Nn);
    // 3b: layer 1 (A1 = node1 K1=256, A2 = mean) -> node2
    gemm_sigmoid_kernel<384><<<(Nn + 31) / 32, 128>>>(node1_p, HDIM, mean_p,
                                                      w1, b1, node2_p, Nn);
    // 4: per-node halves of the final dot product
    {
        long long threads = (long long)Nn * 32;
        pspd_kernel<<<(int)((threads + 255) / 256), 256>>>(wf, Nn);
    }
    // 5: edge embeddings + logits
    {
        long long threads = (long long)E * 32;
        edge_kernel<<<(int)((threads + 255) / 256), 256>>>(edge_index, bf, out, E);
    }
}

// round 3
// speedup vs baseline: 1.6035x; 1.6035x over previous
#include <cuda_runtime.h>
#include <cstdint>

#define NNODES 50000
#define FEDGE  128
#define HDIM   256

// ---------------- scratch (no allocations allowed) ----------------
static __device__ float g_mean[NNODES * FEDGE];   // 25.6 MB
static __device__ float g_cnt[NNODES];
static __device__ float g_node1[NNODES * HDIM];   // 51.2 MB
static __device__ float g_node2[NNODES * HDIM];   // 51.2 MB
static __device__ float g_ps[NNODES];
static __device__ float g_pd[NNODES];

__device__ __forceinline__ int clamp_idx(int v) {
    v = v < 0 ? 0 : v;
    return v >= NNODES ? NNODES - 1 : v;
}

// ---------------- kernel 0: zero the accumulators ----------------
__global__ void zero_kernel() {
    int i = blockIdx.x * blockDim.x + threadIdx.x;
    const int total4 = (NNODES * FEDGE) / 4;
    if (i < total4)
        reinterpret_cast<float4*>(g_mean)[i] = make_float4(0.f, 0.f, 0.f, 0.f);
    if (i < NNODES) g_cnt[i] = 0.f;
}

// ---------------- kernel 1: scatter-add (vector atomics) ----------------
__global__ void scatter_kernel(const float* __restrict__ edge_attr,
                               const int* __restrict__ edge_index,
                               int E) {
    int gt = blockIdx.x * blockDim.x + threadIdx.x;
    int e = gt >> 5;
    int lane = gt & 31;
    if (e >= E) return;
    int src = clamp_idx(edge_index[e]);
    float4 v = reinterpret_cast<const float4*>(edge_attr + (size_t)e * FEDGE)[lane];
    float* dst = g_mean + (size_t)src * FEDGE + lane * 4;
    asm volatile("red.global.add.v4.f32 [%0], {%1,%2,%3,%4};"
                 :: "l"(dst), "f"(v.x), "f"(v.y), "f"(v.z), "f"(v.w) : "memory");
    if (lane == 0) atomicAdd(g_cnt + src, 1.0f);
}

// ---------------- kernel 2: divide by counts (vectorized) ----------------
__global__ void mean_div_kernel() {
    int i = blockIdx.x * blockDim.x + threadIdx.x;  // over float4s
    const int total4 = NNODES * FEDGE / 4;
    if (i < total4) {
        float c = g_cnt[i >> 5];                    // 32 float4 per row
        float inv = 1.0f / fmaxf(c, 1.0f);
        float4 v = reinterpret_cast<float4*>(g_mean)[i];
        v.x *= inv; v.y *= inv; v.z *= inv; v.w *= inv;
        reinterpret_cast<float4*>(g_mean)[i] = v;
    }
}

// ---------------- kernel 3: fused GEMM + bias + sigmoid (register-tiled) ----
// C[M,256] = sigmoid([A1 | A2] @ W + b), A2 = g_mean (row stride 128).
// Block: 256 threads; tile = 32 rows x 256 cols.
// Thread (g,c): rows g*8..g*8+7, cols c*4..c*4+3  (g=tid>>6, c=tid&63).
// Per k: 8 broadcast LDS + 1 LDG.128 (W) + 32 FFMA  -> FFMA ~75% of issue.
template <int K>
__global__ __launch_bounds__(256) void gemm_sigmoid_kernel(
        const float* __restrict__ A1, int K1,
        const float* __restrict__ A2,
        const float* __restrict__ W,
        const float* __restrict__ b,
        float* __restrict__ out, int M) {
    __shared__ float As[32 * K];                    // 32KB / 48KB
    const int tid = threadIdx.x;
    const int row0 = blockIdx.x * 32;
    const int g = tid >> 6;                         // row group 0..3
    const int c = tid & 63;                         // col group 0..63

    // cooperative tile load (float4, coalesced along k)
    {
        const int K4 = K / 4, K14 = K1 / 4;
        const float4* A14 = reinterpret_cast<const float4*>(A1);
        const float4* A24 = reinterpret_cast<const float4*>(A2);
        float4* As4 = reinterpret_cast<float4*>(As);
        for (int idx = tid; idx < 32 * K4; idx += 256) {
            int r = idx / K4;
            int k4 = idx - r * K4;
            int row = row0 + r;
            float4 v = make_float4(0.f, 0.f, 0.f, 0.f);
            if (row < M)
                v = (k4 < K14) ? A14[(size_t)row * K14 + k4]
                               : A24[(size_t)row * (FEDGE / 4) + (k4 - K14)];
            As4[idx] = v;
        }
    }
    __syncthreads();

    float4 acc[8];
#pragma unroll
    for (int i = 0; i < 8; i++) acc[i] = make_float4(0.f, 0.f, 0.f, 0.f);

    const float4* W4 = reinterpret_cast<const float4*>(W);
    const float* Abase = As + (g * 8) * K;

#pragma unroll 4
    for (int k = 0; k < K; k++) {
        float4 w = W4[(size_t)k * 64 + c];          // L2-hot, 512B/warp
        float a[8];
#pragma unroll
        for (int i = 0; i < 8; i++) a[i] = Abase[i * K + k];   // warp broadcast
#pragma unroll
        for (int i = 0; i < 8; i++) {
            acc[i].x += a[i] * w.x;
            acc[i].y += a[i] * w.y;
            acc[i].z += a[i] * w.z;
            acc[i].w += a[i] * w.w;
        }
    }

    float4 bv = reinterpret_cast<const float4*>(b)[c];
#pragma unroll
    for (int i = 0; i < 8; i++) {
        int row = row0 + g * 8 + i;
        if (row < M) {
            float4 x;
            x.x = 1.0f / (1.0f + __expf(-(acc[i].x + bv.x)));
            x.y = 1.0f / (1.0f + __expf(-(acc[i].y + bv.y)));
            x.z = 1.0f / (1.0f + __expf(-(acc[i].z + bv.z)));
            x.w = 1.0f / (1.0f + __expf(-(acc[i].w + bv.w)));
            reinterpret_cast<float4*>(out + (size_t)row * HDIM)[c] = x;
        }
    }
}

// ---------------- kernel 4: per-node partial dot products for logits --------
__global__ void pspd_kernel(const float* __restrict__ wf, int Nn) {
    int gt = blockIdx.x * blockDim.x + threadIdx.x;
    int n = gt >> 5;
    int lane = gt & 31;
    if (n >= Nn) return;
    const float* row = g_node2 + (size_t)n * HDIM;
    float s = 0.f, d = 0.f;
#pragma unroll
    for (int k = lane; k < HDIM; k += 32) {
        float v = row[k];
        s += v * wf[k];
        d += v * wf[HDIM + k];
    }
#pragma unroll
    for (int o = 16; o; o >>= 1) {
        s += __shfl_xor_sync(0xFFFFFFFFu, s, o);
        d += __shfl_xor_sync(0xFFFFFFFFu, d, o);
    }
    if (lane == 0) { g_ps[n] = s; g_pd[n] = d; }
}

// ---------------- kernel 5: edge embeddings + logits ----------------
// Streaming stores (.cs) keep node2 gather table resident in L2.
__global__ void edge_kernel(const int* __restrict__ edge_index,
                            const float* __restrict__ bf,
                            float* __restrict__ out, int E) {
    int gt = blockIdx.x * blockDim.x + threadIdx.x;
    int e = gt >> 5;
    int lane = gt & 31;
    if (e >= E) return;
    int s = clamp_idx(edge_index[e]);
    int d = clamp_idx(edge_index[E + e]);
    const float4* rs = reinterpret_cast<const float4*>(g_node2 + (size_t)s * HDIM);
    const float4* rd = reinterpret_cast<const float4*>(g_node2 + (size_t)d * HDIM);
    float4* o4 = reinterpret_cast<float4*>(out + (size_t)E + (size_t)e * (2 * HDIM));
    __stcs(o4 + lane,      rs[lane]);
    __stcs(o4 + 32 + lane, rs[32 + lane]);
    __stcs(o4 + 64 + lane, rd[lane]);
    __stcs(o4 + 96 + lane, rd[32 + lane]);
    if (lane == 0) __stcs(out + e, g_ps[s] + g_pd[d] + bf[0]);
}

// ---------------- launch ----------------
extern "C" void kernel_launch(void* const* d_in, const int* in_sizes, int n_in,
                              void* d_out, int out_size) {
    const float* edge_attr  = (const float*)d_in[0];
    const int*   edge_index = (const int*)d_in[1];   // int32 per harness contract
    const float* node_attr  = (const float*)d_in[2];
    const float* w0 = (const float*)d_in[3];
    const float* b0 = (const float*)d_in[4];
    const float* w1 = (const float*)d_in[5];
    const float* b1 = (const float*)d_in[6];
    const float* wf = (const float*)d_in[7];
    const float* bf = (const float*)d_in[8];
    float* out = (float*)d_out;

    const int E  = in_sizes[1] / 2;
    const int Nn = in_sizes[2] / FEDGE;

    float *mean_p, *node1_p, *node2_p;
    cudaGetSymbolAddress((void**)&mean_p,  g_mean);
    cudaGetSymbolAddress((void**)&node1_p, g_node1);
    cudaGetSymbolAddress((void**)&node2_p, g_node2);

    {
        int total4 = (NNODES * FEDGE) / 4;
        zero_kernel<<<(total4 + 255) / 256, 256>>>();
    }
    {
        long long threads = (long long)E * 32;
        scatter_kernel<<<(int)((threads + 255) / 256), 256>>>(edge_attr, edge_index, E);
    }
    mean_div_kernel<<<(NNODES * FEDGE / 4 + 255) / 256, 256>>>();

    gemm_sigmoid_kernel<256><<<(Nn + 31) / 32, 256>>>(node_attr, FEDGE, mean_p,
                                                      w0, b0, node1_p, Nn);
    gemm_sigmoid_kernel<384><<<(Nn + 31) / 32, 256>>>(node1_p, HDIM, mean_p,
                                                      w1, b1, node2_p, Nn);
    {
        long long threads = (long long)Nn * 32;
        pspd_kernel<<<(int)((threads + 255) / 256), 256>>>(wf, Nn);
    }
    {
        long long threads = (long long)E * 32;
        edge_kernel<<<(int)((threads + 255) / 256), 256>>>(edge_index, bf, out, E);
    }
}

// round 4
// speedup vs baseline: 1.6578x; 1.0339x over previous
#include <cuda_runtime.h>
#include <cstdint>

#define NNODES 50000
#define FEDGE  128
#define HDIM   256

// ---------------- scratch (no allocations allowed) ----------------
static __device__ float g_mean[NNODES * FEDGE];   // 25.6 MB (raw sums)
static __device__ float g_cnt[NNODES];
static __device__ float g_node1[NNODES * HDIM];   // 51.2 MB
static __device__ float g_node2[NNODES * HDIM];   // 51.2 MB
static __device__ float g_ps[NNODES];
static __device__ float g_pd[NNODES];

__device__ __forceinline__ int clamp_idx(int v) {
    v = v < 0 ? 0 : v;
    return v >= NNODES ? NNODES - 1 : v;
}

// ---------------- kernel 0: zero the accumulators ----------------
__global__ void zero_kernel() {
    int i = blockIdx.x * blockDim.x + threadIdx.x;
    const int total4 = (NNODES * FEDGE) / 4;
    if (i < total4)
        reinterpret_cast<float4*>(g_mean)[i] = make_float4(0.f, 0.f, 0.f, 0.f);
    if (i < NNODES) g_cnt[i] = 0.f;
}

// ---------------- kernel 1: scatter-add (vector atomics) ----------------
__global__ void scatter_kernel(const float* __restrict__ edge_attr,
                               const int* __restrict__ edge_index,
                               int E) {
    int gt = blockIdx.x * blockDim.x + threadIdx.x;
    int e = gt >> 5;
    int lane = gt & 31;
    if (e >= E) return;
    int src = clamp_idx(edge_index[e]);
    float4 v = reinterpret_cast<const float4*>(edge_attr + (size_t)e * FEDGE)[lane];
    float* dst = g_mean + (size_t)src * FEDGE + lane * 4;
    asm volatile("red.global.add.v4.f32 [%0], {%1,%2,%3,%4};"
                 :: "l"(dst), "f"(v.x), "f"(v.y), "f"(v.z), "f"(v.w) : "memory");
    if (lane == 0) atomicAdd(g_cnt + src, 1.0f);
}

// ---------------- kernel 2: fused GEMM + bias + sigmoid --------------------
// C[M,256] = sigmoid([A1 | A2/cnt] @ W + b). A2 = g_mean raw sums; the mean
// division is folded into the tile load (saves a 50MB round-trip kernel).
// Block: 256 threads; tile = 32 rows x 256 cols.
// Thread (g,c): rows g*8..g*8+7, cols c*4..c*4+3.
// Inner: 4-k step = 8 LDS.128 (broadcast) + 4 LDG.128 (W) + 128 FFMA.
template <int K>
__global__ __launch_bounds__(256) void gemm_sigmoid_kernel(
        const float* __restrict__ A1, int K1,
        const float* __restrict__ A2,
        const float* __restrict__ W,
        const float* __restrict__ b,
        float* __restrict__ out, int M) {
    __shared__ float As[32 * K];                    // 32KB / 48KB
    const int tid = threadIdx.x;
    const int row0 = blockIdx.x * 32;
    const int g = tid >> 6;                         // row group 0..3
    const int c = tid & 63;                         // col group 0..63
    const int K4 = K / 4;

    // cooperative tile load (float4, coalesced along k) with mean division
    {
        const int K14 = K1 / 4;
        const float4* A14 = reinterpret_cast<const float4*>(A1);
        const float4* A24 = reinterpret_cast<const float4*>(A2);
        float4* As4 = reinterpret_cast<float4*>(As);
        for (int idx = tid; idx < 32 * K4; idx += 256) {
            int r = idx / K4;
            int k4 = idx - r * K4;
            int row = row0 + r;
            float4 v = make_float4(0.f, 0.f, 0.f, 0.f);
            if (row < M) {
                if (k4 < K14) {
                    v = A14[(size_t)row * K14 + k4];
                } else {
                    v = A24[(size_t)row * (FEDGE / 4) + (k4 - K14)];
                    float inv = 1.0f / fmaxf(g_cnt[row], 1.0f);
                    v.x *= inv; v.y *= inv; v.z *= inv; v.w *= inv;
                }
            }
            As4[idx] = v;
        }
    }
    __syncthreads();

    float4 acc[8];
#pragma unroll
    for (int i = 0; i < 8; i++) acc[i] = make_float4(0.f, 0.f, 0.f, 0.f);

    const float4* W4 = reinterpret_cast<const float4*>(W);
    const float4* Abase4 = reinterpret_cast<const float4*>(As) + (g * 8) * K4;

#pragma unroll 2
    for (int k = 0; k < K; k += 4) {
        const int k4 = k >> 2;
        float4 w0 = W4[(size_t)(k + 0) * 64 + c];   // L2-hot, 512B/warp each
        float4 w1 = W4[(size_t)(k + 1) * 64 + c];
        float4 w2 = W4[(size_t)(k + 2) * 64 + c];
        float4 w3 = W4[(size_t)(k + 3) * 64 + c];
        float4 a4[8];
#pragma unroll
        for (int i = 0; i < 8; i++) a4[i] = Abase4[i * K4 + k4];  // LDS.128 bcast
#pragma unroll
        for (int i = 0; i < 8; i++) {
            acc[i].x += a4[i].x * w0.x; acc[i].y += a4[i].x * w0.y;
            acc[i].z += a4[i].x * w0.z; acc[i].w += a4[i].x * w0.w;
            acc[i].x += a4[i].y * w1.x; acc[i].y += a4[i].y * w1.y;
            acc[i].z += a4[i].y * w1.z; acc[i].w += a4[i].y * w1.w;
            acc[i].x += a4[i].z * w2.x; acc[i].y += a4[i].z * w2.y;
            acc[i].z += a4[i].z * w2.z; acc[i].w += a4[i].z * w2.w;
            acc[i].x += a4[i].w * w3.x; acc[i].y += a4[i].w * w3.y;
            acc[i].z += a4[i].w * w3.z; acc[i].w += a4[i].w * w3.w;
        }
    }

    float4 bv = reinterpret_cast<const float4*>(b)[c];
#pragma unroll
    for (int i = 0; i < 8; i++) {
        int row = row0 + g * 8 + i;
        if (row < M) {
            float4 x;
            x.x = 1.0f / (1.0f + __expf(-(acc[i].x + bv.x)));
            x.y = 1.0f / (1.0f + __expf(-(acc[i].y + bv.y)));
            x.z = 1.0f / (1.0f + __expf(-(acc[i].z + bv.z)));
            x.w = 1.0f / (1.0f + __expf(-(acc[i].w + bv.w)));
            reinterpret_cast<float4*>(out + (size_t)row * HDIM)[c] = x;
        }
    }
}

// ---------------- kernel 3: per-node partial dot products for logits --------
__global__ void pspd_kernel(const float* __restrict__ wf, int Nn) {
    int gt = blockIdx.x * blockDim.x + threadIdx.x;
    int n = gt >> 5;
    int lane = gt & 31;
    if (n >= Nn) return;
    const float4* row = reinterpret_cast<const float4*>(g_node2 + (size_t)n * HDIM);
    const float4* wfs = reinterpret_cast<const float4*>(wf);
    const float4* wfd = reinterpret_cast<const float4*>(wf + HDIM);
    float s = 0.f, d = 0.f;
#pragma unroll
    for (int k = lane; k < HDIM / 4; k += 32) {
        float4 v = row[k];
        float4 a = wfs[k];
        float4 bq = wfd[k];
        s += v.x * a.x + v.y * a.y + v.z * a.z + v.w * a.w;
        d += v.x * bq.x + v.y * bq.y + v.z * bq.z + v.w * bq.w;
    }
#pragma unroll
    for (int o = 16; o; o >>= 1) {
        s += __shfl_xor_sync(0xFFFFFFFFu, s, o);
        d += __shfl_xor_sync(0xFFFFFFFFu, d, o);
    }
    if (lane == 0) { g_ps[n] = s; g_pd[n] = d; }
}

// ---------------- kernel 4: edge embeddings + logits ----------------
// Streaming stores (.cs) keep node2 gather table resident in L2.
__global__ void edge_kernel(const int* __restrict__ edge_index,
                            const float* __restrict__ bf,
                            float* __restrict__ out, int E) {
    int gt = blockIdx.x * blockDim.x + threadIdx.x;
    int e = gt >> 5;
    int lane = gt & 31;
    if (e >= E) return;
    int s = clamp_idx(edge_index[e]);
    int d = clamp_idx(edge_index[E + e]);
    const float4* rs = reinterpret_cast<const float4*>(g_node2 + (size_t)s * HDIM);
    const float4* rd = reinterpret_cast<const float4*>(g_node2 + (size_t)d * HDIM);
    float4* o4 = reinterpret_cast<float4*>(out + (size_t)E + (size_t)e * (2 * HDIM));
    __stcs(o4 + lane,      rs[lane]);
    __stcs(o4 + 32 + lane, rs[32 + lane]);
    __stcs(o4 + 64 + lane, rd[lane]);
    __stcs(o4 + 96 + lane, rd[32 + lane]);
    if (lane == 0) __stcs(out + e, g_ps[s] + g_pd[d] + bf[0]);
}

// ---------------- launch ----------------
extern "C" void kernel_launch(void* const* d_in, const int* in_sizes, int n_in,
                              void* d_out, int out_size) {
    const float* edge_attr  = (const float*)d_in[0];
    const int*   edge_index = (const int*)d_in[1];   // int32 per harness contract
    const float* node_attr  = (const float*)d_in[2];
    const float* w0 = (const float*)d_in[3];
    const float* b0 = (const float*)d_in[4];
    const float* w1 = (const float*)d_in[5];
    const float* b1 = (const float*)d_in[6];
    const float* wf = (const float*)d_in[7];
    const float* bf = (const float*)d_in[8];
    float* out = (float*)d_out;

    const int E  = in_sizes[1] / 2;
    const int Nn = in_sizes[2] / FEDGE;

    float *mean_p, *node1_p, *node2_p;
    cudaGetSymbolAddress((void**)&mean_p,  g_mean);
    cudaGetSymbolAddress((void**)&node1_p, g_node1);
    cudaGetSymbolAddress((void**)&node2_p, g_node2);

    {
        int total4 = (NNODES * FEDGE) / 4;
        zero_kernel<<<(total4 + 255) / 256, 256>>>();
    }
    {
        long long threads = (long long)E * 32;
        scatter_kernel<<<(int)((threads + 255) / 256), 256>>>(edge_attr, edge_index, E);
    }

    gemm_sigmoid_kernel<256><<<(Nn + 31) / 32, 256>>>(node_attr, FEDGE, mean_p,
                                                      w0, b0, node1_p, Nn);
    gemm_sigmoid_kernel<384><<<(Nn + 31) / 32, 256>>>(node1_p, HDIM, mean_p,
                                                      w1, b1, node2_p, Nn);
    {
        long long threads = (long long)Nn * 32;
        pspd_kernel<<<(int)((threads + 255) / 256), 256>>>(wf, Nn);
    }
    {
        long long threads = (long long)E * 32;
        edge_kernel<<<(int)((threads + 255) / 256), 256>>>(edge_index, bf, out, E);
    }
}